// round 10
// baseline (speedup 1.0000x reference)
#include <cuda_runtime.h>

// ---------------------------------------------------------------------------
// Quantized LSTM with LAG-2 deferred scale verification.
//  - Blocks couple ONLY through po2 scale exponents; all exponents are
//    predicted (= last verified values) and verified 2 steps later, so the
//    grid barrier latency overlaps with 2 compute phases.
//  - Per-step cells AND per-step counters (slot 8) -> no sum-counter
//    ambiguity for pipelined fires. Resync fixups use a cumulative counter
//    (every add gated on the previous wait -> safe by induction).
//  - On any miss (globally uniform): synchronous resync replays the window
//    (<=3 steps) from h/c/x ring buffers with R6's exact tiered logic on
//    spare cell slots, rewrites h/c/out, updates predictions, advances vptr.
// ---------------------------------------------------------------------------

#define GB       128
#define BPB      8
#define NT       640
#define T_STEPS  1024
#define NI       10
#define NH       20
#define NG       80
#define CSTRIDE  64              // 256B between cells
#define NCELL    24              // 0-7 main, 8 counter, 9-16 replayA, 17 B, 18-19 C, 20 D
#define LAG      2
#define RB       4               // ring depth for h/c/x history

__device__ __align__(128) unsigned g_ctr1[32];             // resync round counter
__device__ unsigned g_cells[T_STEPS * NCELL * CSTRIDE];

__global__ void qlstm_init() {
    int i = blockIdx.x * blockDim.x + threadIdx.x;          // 24576 = T_STEPS*NCELL
    if (i == 0) g_ctr1[0] = 0u;
    if (i < T_STEPS * NCELL) g_cells[i * CSTRIDE] = 0u;
}

__device__ __forceinline__ unsigned mapf(float f) {
    unsigned u = __float_as_uint(f);
    return (u & 0x80000000u) ? ~u : (u | 0x80000000u);
}
__device__ __forceinline__ float unmapf(unsigned u) {
    return __uint_as_float((u & 0x80000000u) ? (u & 0x7FFFFFFFu) : ~u);
}
__device__ __forceinline__ int po2k(float m) {
    m = fmaxf(m, 1e-8f);
    int e; float f = frexpf(m, &e);
    return (f == 0.5f) ? (e - 1) : e;
}
__device__ __forceinline__ float sc(int k)    { return __uint_as_float((unsigned)(k + 120) << 23); }
__device__ __forceinline__ float scinv(int k) { return __uint_as_float((unsigned)(134 - k) << 23); }
__device__ __forceinline__ float fq1(float x, float s, float inv) {
    float q = rintf(x * inv);
    q = fminf(fmaxf(q, -128.0f), 127.0f);
    return q * s;
}
__device__ __forceinline__ float sigm(float x) { return 1.0f / (1.0f + expf(-x)); }
__device__ __forceinline__ unsigned warp_max_u(unsigned v) {
#pragma unroll
    for (int o = 16; o; o >>= 1) v = max(v, __shfl_xor_sync(0xffffffffu, v, o));
    return v;
}
__device__ __forceinline__ void red_max_rlx(unsigned* p, unsigned v) {
    asm volatile("red.relaxed.gpu.max.u32 [%0],%1;" :: "l"(p), "r"(v) : "memory");
}
__device__ __forceinline__ void red_add_rel(unsigned* p, unsigned v) {
    asm volatile("red.release.gpu.add.u32 [%0],%1;" :: "l"(p), "r"(v) : "memory");
}
__device__ __forceinline__ unsigned ld_acq(const unsigned* p) {
    unsigned v; asm volatile("ld.acquire.gpu.u32 %0,[%1];" : "=r"(v) : "l"(p) : "memory"); return v;
}
__device__ __forceinline__ unsigned ld_rlx(const unsigned* p) {
    unsigned v; asm volatile("ld.relaxed.gpu.u32 %0,[%1];" : "=r"(v) : "l"(p) : "memory"); return v;
}

// synchronous resync round on the cumulative counter g_ctr1
__device__ __forceinline__ unsigned grid_round1(unsigned* cell0, unsigned myv, int nc,
                                                unsigned tgt, int lane) {
    if (lane < nc) red_max_rlx(cell0 + lane * CSTRIDE, myv);
    __syncwarp();
    if (lane == 0) red_add_rel(&g_ctr1[0], 1u);
    if (lane < nc) { while (ld_acq(&g_ctr1[0]) < tgt) { } }
    __syncwarp();
    return (lane < nc) ? ld_rlx(cell0 + lane * CSTRIDE) : 0u;
}

__global__ void __launch_bounds__(NT, 1) qlstm_main(
    const float* __restrict__ x,
    const float* __restrict__ Wih,
    const float* __restrict__ Whh,
    float* __restrict__ out)
{
    __shared__ __align__(16) float sh_h[RB][BPB * NH];   // h ring
    __shared__ __align__(16) float sh_c[RB][160];        // c ring
    __shared__ __align__(16) float sh_x[RB][BPB * NI];   // x ring
    __shared__ float               sh_act[NG * BPB];
    __shared__ unsigned            sh_red[12];
    __shared__ int                 sh_k[8];   // 0:k1 1-4:ka 5:k3 6:kh 7:code/flag
    __shared__ int                 sh_vp;     // next step to verify

    const int tid  = threadIdx.x;
    const int g    = tid / BPB;          // gate row 0..79
    const int b    = tid % BPB;          // local batch 0..7
    const int gr   = tid / 160;          // gate group (warp-uniform)
    const int lane = tid & 31;
    const int wid  = tid >> 5;

    if (tid < 12) sh_red[tid] = 0u;
    if (tid == 0) { sh_k[0] = 1; sh_k[5] = 0; sh_k[6] = 0; sh_k[7] = 0; sh_vp = 0; }
    if (tid >= 1 && tid <= 4) sh_k[tid] = 0;          // plausible warm-start preds
    if (tid < BPB * NH) { sh_h[0][tid] = 0.0f; sh_h[1][tid] = 0.0f;
                          sh_h[2][tid] = 0.0f; sh_h[3][tid] = 0.0f; }
    if (tid < 160)      { sh_c[0][tid] = 0.0f; sh_c[1][tid] = 0.0f;
                          sh_c[2][tid] = 0.0f; sh_c[3][tid] = 0.0f; }
    __syncthreads();

    // ---- weight scale (block-local, once) ----
    {
        float wm = 0.0f;
        for (int k = tid; k < NG * NI; k += NT) wm = fmaxf(wm, fabsf(Wih[k]));
        for (int k = tid; k < NG * NH; k += NT) wm = fmaxf(wm, fabsf(Whh[k]));
        unsigned u = warp_max_u(__float_as_uint(wm));
        if (lane == 0) atomicMax(&sh_red[11], u);
        __syncthreads();
    }
    int kw = po2k(__uint_as_float(sh_red[11]));
    float ws = sc(kw), wsi = scinv(kw);
    __syncthreads();
    if (tid == 0) sh_red[11] = 0u;
    __syncthreads();

    float wi[NI], wh[NH];
#pragma unroll
    for (int i2 = 0; i2 < NI; i2++) wi[i2] = fq1(Wih[g * NI + i2], ws, wsi);
#pragma unroll
    for (int j2 = 0; j2 < NH; j2++) wh[j2] = fq1(Whh[g * NH + j2], ws, wsi);

    float    c_reg = 0.0f;
    unsigned nbarR = 0;                  // resync round index (uniform)

    const int sq  = tid - 560;           // warps 17-19 stage x
    const int sxb = (sq >= 0) ? sq / NI : 0;
    const int sxi = (sq >= 0) ? sq % NI : 0;
    float xr = 0.0f;
    if (sq >= 0) {
        sh_x[0][sq] = x[((size_t)(blockIdx.x * BPB + sxb) * T_STEPS + 0) * NI + sxi];
        xr          = x[((size_t)(blockIdx.x * BPB + sxb) * T_STEPS + 1) * NI + sxi];
    }
    __syncthreads();

    for (int t = 0; t < T_STEPS + LAG; ++t) {
        const int tEnd = (t < T_STEPS) ? t : (T_STEPS - 1);

        // ================= COMPUTE + FIRE step t (speculative) =================
        if (t < T_STEPS) {
            const int k1p = sh_k[0], kap = sh_k[1 + gr], k3p = sh_k[5], khp = sh_k[6];

            float p0 = 0.0f, p1 = 0.0f;
            {
                const float2* px = reinterpret_cast<const float2*>(&sh_x[t & 3][b * NI]);
                const float2* ph = reinterpret_cast<const float2*>(&sh_h[(t + 3) & 3][b * NH]);
#pragma unroll
                for (int j = 0; j < NI / 2; j++) {
                    float2 v = px[j];
                    p0 = fmaf(v.x, wi[2 * j], p0); p1 = fmaf(v.y, wi[2 * j + 1], p1);
                }
#pragma unroll
                for (int j = 0; j < NH / 2; j++) {
                    float2 v = ph[j];
                    p0 = fmaf(v.x, wh[2 * j], p0); p1 = fmaf(v.y, wh[2 * j + 1], p1);
                }
            }
            float pre = p0 + p1;
            unsigned kp = warp_max_u(mapf(pre));
            unsigned kn = warp_max_u(mapf(-pre));
            if (lane == 0) { atomicMax(&sh_red[gr], kp); atomicMax(&sh_red[4 + gr], kn); }
            {
                float gq  = fq1(pre, sc(k1p), scinv(k1p));
                float act = (gr == 2) ? tanhf(gq) : sigm(gq);
                sh_act[tid] = fq1(act, sc(kap), scinv(kap));
            }
            __syncthreads();                                    // S1
            if (sq >= 0 && t + 1 < T_STEPS) sh_x[(t + 1) & 3][sq] = xr;

            float tc = 0.0f, hp = 0.0f;
            if (tid < 160) {
                float iq = sh_act[tid], ff = sh_act[tid + 160], gg = sh_act[tid + 320];
                float oq = sh_act[tid + 480];
                c_reg = ff * c_reg + iq * gg;
                sh_c[t & 3][tid] = c_reg;
                tc = tanhf(c_reg);
                hp = oq * fq1(tc, sc(k3p), scinv(k3p));
                float hq = fq1(hp, sc(khp), scinv(khp));
                sh_h[t & 3][b * NH + g] = hq;
                out[((size_t)(blockIdx.x * BPB + b) * T_STEPS + t) * NH + g] = hq;
            }
            if (wid < 5) {
                unsigned a1 = warp_max_u(__float_as_uint(fabsf(tc)));
                unsigned a2 = warp_max_u(__float_as_uint(fabsf(hp)));
                if (lane == 0) { atomicMax(&sh_red[8], a1); atomicMax(&sh_red[9], a2); }
            }
            if (sq >= 0 && t + 2 < T_STEPS)
                xr = x[((size_t)(blockIdx.x * BPB + sxb) * T_STEPS + (t + 2)) * NI + sxi];
            __syncthreads();                                    // S2

            // fire reductions for step t (no wait)
            if (wid == 0) {
                unsigned v = (lane < 10) ? sh_red[lane] : 0u;
                __syncwarp();
                if (lane < 10) sh_red[lane] = 0u;
                unsigned n0 = __shfl_sync(0xffffffffu, v, 4);
                unsigned n1 = __shfl_sync(0xffffffffu, v, 5);
                unsigned n2 = __shfl_sync(0xffffffffu, v, 6);
                unsigned n3 = __shfl_sync(0xffffffffu, v, 7);
                unsigned t8 = __shfl_sync(0xffffffffu, v, 8);
                unsigned t9 = __shfl_sync(0xffffffffu, v, 9);
                unsigned myv = v;
                if (lane == 4) myv = n2;
                if (lane == 5) myv = max(max(n0, n1), max(n2, n3));
                if (lane == 6) myv = t8;
                if (lane == 7) myv = t9;
                unsigned* cb = &g_cells[(size_t)t * NCELL * CSTRIDE];
                if (lane < 8) red_max_rlx(cb + lane * CSTRIDE, myv);
                __syncwarp();
                if (lane == 0) red_add_rel(cb + 8 * CSTRIDE, 1u);
            }
        }

        // ================= VERIFY step s = t - LAG =================
        const int s = t - LAG;
        const int svp = sh_vp;           // stable: last write was before a sync
        if (s >= 0 && s >= svp) {
            if (wid == 0) {
                unsigned* cbs = &g_cells[(size_t)svp * NCELL * CSTRIDE];
                if (lane < 8) { while (ld_acq(cbs + 8 * CSTRIDE) < GB) { } }
                __syncwarp();
                unsigned cv = (lane < 8) ? ld_rlx(cbs + lane * CSTRIDE) : 0u;
                unsigned kk = (lane < 4 || lane == 5) ? cv : 0u;
                kk = max(kk, __shfl_xor_sync(0xffffffffu, kk, 4));
                kk = max(kk, __shfl_xor_sync(0xffffffffu, kk, 2));
                kk = max(kk, __shfl_xor_sync(0xffffffffu, kk, 1));
                int k1 = po2k(unmapf(kk));
                k1 = __shfl_sync(0xffffffffu, k1, 0);
                float s1 = sc(k1), v1 = scinv(k1);
                float mng = unmapf(__shfl_sync(0xffffffffu, cv, 4));
                float myp = unmapf(cv);
                float a;
                if (lane == 2) {
                    float q1 = fq1(myp, s1, v1), q2 = fq1(-mng, s1, v1);
                    a = tanhf(fmaxf(q1, -q2));
                } else {
                    a = sigm(fq1(myp, s1, v1));
                }
                int ka  = po2k(fabsf(a));
                int k3t = po2k(__uint_as_float(__shfl_sync(0xffffffffu, cv, 6)));
                int kht = po2k(__uint_as_float(__shfl_sync(0xffffffffu, cv, 7)));
                bool okl = (lane < 4) ? (ka == sh_k[1 + lane]) : true;
                unsigned bm = __ballot_sync(0xffffffffu, okl);
                int hit1 = (((bm & 0xFu) == 0xFu) && (k1 == sh_k[0])) ? 1 : 0;
                int hit3 = (k3t == sh_k[5]) ? 1 : 0;
                int hith = (kht == sh_k[6]) ? 1 : 0;
                int code = hit1 ? (hit3 ? (hith ? 0 : 1) : 2) : 3;
                if (lane < 4) sh_k[1 + lane] = ka;               // gate cells always exact
                if (lane == 0) {
                    sh_k[0] = k1;
                    if (hit1) sh_k[5] = k3t;
                    if (hit1 && hit3) sh_k[6] = kht;
                    sh_k[7] = code;
                    if (code == 0) sh_vp = svp + 1;
                }
            }
            __syncthreads();                                    // S3

            if (sh_k[7] != 0) {
                // ============ RESYNC: replay steps svp..tEnd synchronously ============
                for (int u = svp; u <= tEnd; ++u) {
                    unsigned* cu = &g_cells[(size_t)u * NCELL * CSTRIDE];
                    const int k1p = sh_k[0], kap = sh_k[1 + gr], k3p = sh_k[5];
                    // phase B from rings
                    float p0 = 0.0f, p1 = 0.0f;
                    {
                        const float2* px = reinterpret_cast<const float2*>(&sh_x[u & 3][b * NI]);
                        const float2* ph = reinterpret_cast<const float2*>(&sh_h[(u + 3) & 3][b * NH]);
#pragma unroll
                        for (int j = 0; j < NI / 2; j++) {
                            float2 v = px[j];
                            p0 = fmaf(v.x, wi[2 * j], p0); p1 = fmaf(v.y, wi[2 * j + 1], p1);
                        }
#pragma unroll
                        for (int j = 0; j < NH / 2; j++) {
                            float2 v = ph[j];
                            p0 = fmaf(v.x, wh[2 * j], p0); p1 = fmaf(v.y, wh[2 * j + 1], p1);
                        }
                    }
                    float pre = p0 + p1;
                    unsigned kp = warp_max_u(mapf(pre));
                    unsigned kn = warp_max_u(mapf(-pre));
                    if (lane == 0) { atomicMax(&sh_red[gr], kp); atomicMax(&sh_red[4 + gr], kn); }
                    {
                        float gq  = fq1(pre, sc(k1p), scinv(k1p));
                        float act = (gr == 2) ? tanhf(gq) : sigm(gq);
                        sh_act[tid] = fq1(act, sc(kap), scinv(kap));
                    }
                    __syncthreads();
                    float cold = 0.0f, cnew = 0.0f, tc = 0.0f, oq = 0.0f, hp = 0.0f;
                    if (tid < 160) {
                        float iq = sh_act[tid], ff = sh_act[tid + 160], gg = sh_act[tid + 320];
                        oq = sh_act[tid + 480];
                        cold = sh_c[(u + 3) & 3][tid];
                        cnew = ff * cold + iq * gg;
                        tc = tanhf(cnew);
                        hp = oq * fq1(tc, sc(k3p), scinv(k3p));
                    }
                    if (wid < 5) {
                        unsigned a1 = warp_max_u(__float_as_uint(fabsf(tc)));
                        unsigned a2 = warp_max_u(__float_as_uint(fabsf(hp)));
                        if (lane == 0) { atomicMax(&sh_red[8], a1); atomicMax(&sh_red[9], a2); }
                    }
                    __syncthreads();
                    // round A (slots 9-16)
                    nbarR++;
                    if (wid == 0) {
                        unsigned v = (lane < 10) ? sh_red[lane] : 0u;
                        __syncwarp();
                        if (lane < 10) sh_red[lane] = 0u;
                        unsigned n0 = __shfl_sync(0xffffffffu, v, 4);
                        unsigned n1 = __shfl_sync(0xffffffffu, v, 5);
                        unsigned n2 = __shfl_sync(0xffffffffu, v, 6);
                        unsigned n3 = __shfl_sync(0xffffffffu, v, 7);
                        unsigned t8 = __shfl_sync(0xffffffffu, v, 8);
                        unsigned t9 = __shfl_sync(0xffffffffu, v, 9);
                        unsigned myv = v;
                        if (lane == 4) myv = n2;
                        if (lane == 5) myv = max(max(n0, n1), max(n2, n3));
                        if (lane == 6) myv = t8;
                        if (lane == 7) myv = t9;
                        unsigned cv = grid_round1(cu + 9 * CSTRIDE, myv, 8, nbarR * GB, lane);
                        unsigned kk = (lane < 4 || lane == 5) ? cv : 0u;
                        kk = max(kk, __shfl_xor_sync(0xffffffffu, kk, 4));
                        kk = max(kk, __shfl_xor_sync(0xffffffffu, kk, 2));
                        kk = max(kk, __shfl_xor_sync(0xffffffffu, kk, 1));
                        int k1 = po2k(unmapf(kk));
                        k1 = __shfl_sync(0xffffffffu, k1, 0);
                        float s1 = sc(k1), v1 = scinv(k1);
                        float mng = unmapf(__shfl_sync(0xffffffffu, cv, 4));
                        float myp = unmapf(cv);
                        float a;
                        if (lane == 2) {
                            float q1 = fq1(myp, s1, v1), q2 = fq1(-mng, s1, v1);
                            a = tanhf(fmaxf(q1, -q2));
                        } else {
                            a = sigm(fq1(myp, s1, v1));
                        }
                        int ka  = po2k(fabsf(a));
                        int k3t = po2k(__uint_as_float(__shfl_sync(0xffffffffu, cv, 6)));
                        int kht = po2k(__uint_as_float(__shfl_sync(0xffffffffu, cv, 7)));
                        bool okl = (lane < 4) ? (ka == sh_k[1 + lane]) : true;
                        unsigned bm = __ballot_sync(0xffffffffu, okl);
                        int hit1 = (((bm & 0xFu) == 0xFu) && (k1 == sh_k[0])) ? 1 : 0;
                        int hit3 = (k3t == sh_k[5]) ? 1 : 0;
                        int hith = (kht == sh_k[6]) ? 1 : 0;
                        int code = hit1 ? (hit3 ? (hith ? 0 : 1) : 2) : 3;
                        if (lane < 4) sh_k[1 + lane] = ka;
                        if (lane == 0) {
                            sh_k[0] = k1;
                            if (hit1) sh_k[5] = k3t;
                            if (hit1 && hit3) sh_k[6] = kht;
                            sh_k[7] = code;
                        }
                    }
                    __syncthreads();
                    int code = sh_k[7];
                    if (code == 2) {
                        // k3 miss (tc exact): true-k3 hp, one round for kh (slot 17)
                        float s3 = sc(sh_k[5]), v3 = scinv(sh_k[5]);
                        if (tid < 160) hp = oq * fq1(tc, s3, v3);
                        if (wid < 5) {
                            unsigned a2 = warp_max_u(__float_as_uint(fabsf(hp)));
                            if (lane == 0) atomicMax(&sh_red[9], a2);
                        }
                        __syncthreads();
                        nbarR++;
                        if (wid == 0) {
                            unsigned v = (lane == 0) ? sh_red[9] : 0u;
                            __syncwarp();
                            if (lane == 0) sh_red[9] = 0u;
                            unsigned cv = grid_round1(cu + 17 * CSTRIDE, v, 1, nbarR * GB, lane);
                            if (lane == 0) sh_k[6] = po2k(__uint_as_float(cv));
                        }
                        __syncthreads();
                    } else if (code == 3) {
                        // full miss: recompute with exact k1/ka; rounds C (18-19), maybe D (20)
                        {
                            int k1 = sh_k[0], kat = sh_k[1 + gr];
                            float gq  = fq1(pre, sc(k1), scinv(k1));
                            float act = (gr == 2) ? tanhf(gq) : sigm(gq);
                            sh_act[tid] = fq1(act, sc(kat), scinv(kat));
                        }
                        __syncthreads();
                        int k3g = sh_k[5];
                        if (tid < 160) {
                            float iq = sh_act[tid], ff = sh_act[tid + 160], gg = sh_act[tid + 320];
                            oq = sh_act[tid + 480];
                            cnew = ff * cold + iq * gg;
                            tc = tanhf(cnew);
                            hp = oq * fq1(tc, sc(k3g), scinv(k3g));
                        }
                        if (wid < 5) {
                            unsigned a1 = warp_max_u(__float_as_uint(fabsf(tc)));
                            unsigned a2 = warp_max_u(__float_as_uint(fabsf(hp)));
                            if (lane == 0) { atomicMax(&sh_red[8], a1); atomicMax(&sh_red[9], a2); }
                        }
                        __syncthreads();
                        nbarR++;
                        if (wid == 0) {
                            unsigned v = 0u;
                            if (lane == 0) v = sh_red[8];
                            if (lane == 1) v = sh_red[9];
                            __syncwarp();
                            if (lane < 2) sh_red[8 + lane] = 0u;
                            unsigned cv = grid_round1(cu + 18 * CSTRIDE, v, 2, nbarR * GB, lane);
                            int kx = po2k(__uint_as_float(cv));
                            int k3 = __shfl_sync(0xffffffffu, kx, 0);
                            int kh = __shfl_sync(0xffffffffu, kx, 1);
                            if (lane == 0) {
                                sh_k[5] = k3; sh_k[6] = kh;
                                sh_k[7] = (k3 == k3g) ? 0 : 1;
                            }
                        }
                        __syncthreads();
                        if (sh_k[7]) {          // k3 guess missed: round D
                            float s3 = sc(sh_k[5]), v3 = scinv(sh_k[5]);
                            if (tid < 160) hp = oq * fq1(tc, s3, v3);
                            if (wid < 5) {
                                unsigned a2 = warp_max_u(__float_as_uint(fabsf(hp)));
                                if (lane == 0) atomicMax(&sh_red[9], a2);
                            }
                            __syncthreads();
                            nbarR++;
                            if (wid == 0) {
                                unsigned v = (lane == 0) ? sh_red[9] : 0u;
                                __syncwarp();
                                if (lane == 0) sh_red[9] = 0u;
                                unsigned cv = grid_round1(cu + 20 * CSTRIDE, v, 1, nbarR * GB, lane);
                                if (lane == 0) sh_k[6] = po2k(__uint_as_float(cv));
                            }
                            __syncthreads();
                        }
                    }
                    // write corrected h/c/out for step u
                    if (tid < 160) {
                        float sh_ = sc(sh_k[6]), vh_ = scinv(sh_k[6]);
                        float hq = fq1(hp, sh_, vh_);
                        sh_h[u & 3][b * NH + g] = hq;
                        sh_c[u & 3][tid] = cnew;
                        c_reg = cnew;
                        out[((size_t)(blockIdx.x * BPB + b) * T_STEPS + u) * NH + g] = hq;
                    }
                    __syncthreads();
                }
                if (tid == 0) { sh_vp = tEnd + 1; sh_k[7] = 0; }
                __syncthreads();
            }
        } else {
            __syncthreads();                                    // cover sh_red reset
        }
    }
}

extern "C" void kernel_launch(void* const* d_in, const int* in_sizes, int n_in,
                              void* d_out, int out_size) {
    (void)in_sizes; (void)n_in; (void)out_size;
    qlstm_init<<<48, 512>>>();
    qlstm_main<<<GB, NT>>>((const float*)d_in[0],
                           (const float*)d_in[1],
                           (const float*)d_in[2],
                           (float*)d_out);
}